// round 1
// baseline (speedup 1.0000x reference)
#include <cuda_runtime.h>
#include <cstdint>

// Problem constants
#define HH   4
#define HDm  256
#define Dm   1024
#define Sm   4096
#define Bm   8
#define MTOK (Bm * Sm)   // 32768 tokens

// Gate scratch: (z,i,f,o) interleaved per (token, d).  32768*1024*16B = 512 MB.
__device__ float4 g_gates[(size_t)MTOK * Dm];

// ---------------------------------------------------------------------------
// tf32 helpers
// ---------------------------------------------------------------------------
__device__ __forceinline__ float f2tf32(float x) {
    unsigned u;
    asm("cvt.rna.tf32.f32 %0, %1;" : "=r"(u) : "f"(x));
    return __uint_as_float(u);
}

__device__ __forceinline__ void mma_tf32(float c[4], const unsigned a[4], const unsigned b[2]) {
    asm volatile(
        "mma.sync.aligned.m16n8k8.row.col.f32.tf32.tf32.f32 "
        "{%0,%1,%2,%3}, {%4,%5,%6,%7}, {%8,%9}, {%0,%1,%2,%3};"
        : "+f"(c[0]), "+f"(c[1]), "+f"(c[2]), "+f"(c[3])
        : "r"(a[0]), "r"(a[1]), "r"(a[2]), "r"(a[3]), "r"(b[0]), "r"(b[1]));
}

// ---------------------------------------------------------------------------
// Pregate GEMM:  per head h,  out[t, n] = sum_k x[t, h*256+k] * Wg[h][o][k]
// with n = o*4 + g  (gate-interleaved so epilogue writes are contiguous).
// BM=64, BN=128, BK=32, 256 threads (8 warps as 2m x 4n, warp tile 32x32).
// ---------------------------------------------------------------------------
#define BM 64
#define BN 128
#define BK 32

__global__ __launch_bounds__(256) void pregate_gemm(
    const float* __restrict__ x,
    const float* __restrict__ Wz, const float* __restrict__ Wi,
    const float* __restrict__ Wf, const float* __restrict__ Wo)
{
    __shared__ float As[BM][BK + 1];   // [m][k], tf32-rounded
    __shared__ float Bs[BN][BK + 1];   // [n][k], tf32-rounded

    const int h  = blockIdx.z;
    const int m0 = blockIdx.x * BM;
    const int n0 = blockIdx.y * BN;
    const int tid  = threadIdx.x;
    const int lane = tid & 31;
    const int wid  = tid >> 5;
    const int wm = wid & 1;       // 2 warps along m (32 rows each)
    const int wn = wid >> 1;      // 4 warps along n (32 cols each)
    const int grp = lane >> 2;    // 0..7
    const int tig = lane & 3;     // 0..3

    const float* Wg[4] = {Wz, Wi, Wf, Wo};

    float acc[2][4][4];
    #pragma unroll
    for (int mf = 0; mf < 2; mf++)
        #pragma unroll
        for (int nf = 0; nf < 4; nf++)
            #pragma unroll
            for (int i = 0; i < 4; i++) acc[mf][nf][i] = 0.0f;

    const int lr  = tid >> 3;        // 0..31
    const int lc4 = (tid & 7) * 4;   // 0..28

    for (int k0 = 0; k0 < HDm; k0 += BK) {
        // Load A tile (64x32): 2 float4 per thread
        #pragma unroll
        for (int rr = 0; rr < BM; rr += 32) {
            const float4 v = *(const float4*)&x[(size_t)(m0 + lr + rr) * Dm + h * HDm + k0 + lc4];
            As[lr + rr][lc4 + 0] = f2tf32(v.x);
            As[lr + rr][lc4 + 1] = f2tf32(v.y);
            As[lr + rr][lc4 + 2] = f2tf32(v.z);
            As[lr + rr][lc4 + 3] = f2tf32(v.w);
        }
        // Load B tile (128x32): 4 float4 per thread. Row n -> gate g=n&3, o=n>>2.
        #pragma unroll
        for (int rr = 0; rr < BN; rr += 32) {
            const int n = n0 + lr + rr;
            const int g = n & 3;
            const int o = n >> 2;
            const float4 v = *(const float4*)&Wg[g][((size_t)(h * HDm + o)) * HDm + k0 + lc4];
            Bs[lr + rr][lc4 + 0] = f2tf32(v.x);
            Bs[lr + rr][lc4 + 1] = f2tf32(v.y);
            Bs[lr + rr][lc4 + 2] = f2tf32(v.z);
            Bs[lr + rr][lc4 + 3] = f2tf32(v.w);
        }
        __syncthreads();

        #pragma unroll
        for (int kk = 0; kk < BK; kk += 8) {
            unsigned a[2][4];
            #pragma unroll
            for (int mf = 0; mf < 2; mf++) {
                const int mr = wm * 32 + mf * 16;
                a[mf][0] = __float_as_uint(As[mr + grp    ][kk + tig    ]);
                a[mf][1] = __float_as_uint(As[mr + grp + 8][kk + tig    ]);
                a[mf][2] = __float_as_uint(As[mr + grp    ][kk + tig + 4]);
                a[mf][3] = __float_as_uint(As[mr + grp + 8][kk + tig + 4]);
            }
            unsigned bf[4][2];
            #pragma unroll
            for (int nf = 0; nf < 4; nf++) {
                const int nc = wn * 32 + nf * 8 + grp;
                bf[nf][0] = __float_as_uint(Bs[nc][kk + tig    ]);
                bf[nf][1] = __float_as_uint(Bs[nc][kk + tig + 4]);
            }
            #pragma unroll
            for (int mf = 0; mf < 2; mf++)
                #pragma unroll
                for (int nf = 0; nf < 4; nf++)
                    mma_tf32(acc[mf][nf], a[mf], bf[nf]);
        }
        __syncthreads();
    }

    // Epilogue: out float index = t*4096 + h*1024 + n  (contiguous in n)
    float* out = (float*)g_gates;
    #pragma unroll
    for (int mf = 0; mf < 2; mf++) {
        #pragma unroll
        for (int nf = 0; nf < 4; nf++) {
            const int row = m0 + wm * 32 + mf * 16 + grp;
            const int col = n0 + wn * 32 + nf * 8 + 2 * tig;
            float* o0 = out + (size_t)row * 4096 + h * 1024 + col;
            *(float2*)o0                        = make_float2(acc[mf][nf][0], acc[mf][nf][1]);
            *(float2*)(o0 + (size_t)8 * 4096)   = make_float2(acc[mf][nf][2], acc[mf][nf][3]);
        }
    }
}

// ---------------------------------------------------------------------------
// Sequential scan: 8192 lanes (b,d), 4096 steps each. 64 blocks x 128 thr
// (1 warp per SMSP on 64 SMs -> full per-warp MUFU rate).
// Single-exp stabilized update: one of f_hat/i_hat is exactly 1.
// ---------------------------------------------------------------------------
#define PF 8

__global__ __launch_bounds__(128) void slstm_scan(float* __restrict__ out)
{
    const int gt = blockIdx.x * 128 + threadIdx.x;  // 0..8191
    const int b = gt >> 10;
    const int d = gt & 1023;

    const float4* gp = g_gates + (size_t)b * Sm * Dm + d;
    float* op = out + (size_t)b * Sm * Dm + d;

    float c = 0.0f, n = 0.0f, m = 0.0f;

    float4 buf[PF];
    #pragma unroll
    for (int j = 0; j < PF; j++) buf[j] = gp[(size_t)j * Dm];

    for (int s0 = 0; s0 < Sm; s0 += PF) {
        #pragma unroll
        for (int j = 0; j < PF; j++) {
            const float4 gv = buf[j];
            const int sn = s0 + j + PF;
            if (sn < Sm) buf[j] = gp[(size_t)sn * Dm];

            const float zt = gv.x, it = gv.y, ft = gv.z, ot = gv.w;

            // m' = max(f + m, i); one exp for the non-dominant branch
            const float fm = ft + m;
            const bool  fge = (fm >= it);
            const float e  = __expf(-fabsf(fm - it));
            const float i_hat = fge ? e : 1.0f;
            const float f_hat = fge ? 1.0f : e;
            m = fmaxf(fm, it);

            // z = tanh(zt) = 1 - 2/(exp(2z)+1)   (exact at +/-inf limits)
            const float z = 1.0f - __fdividef(2.0f, __expf(2.0f * zt) + 1.0f);
            // o = sigmoid(ot)
            const float o = __fdividef(1.0f, 1.0f + __expf(-ot));

            c = f_hat * c + i_hat * z;
            n = f_hat * n + i_hat;

            op[(size_t)(s0 + j) * Dm] = o * __fdividef(c, n + 1e-8f);
        }
    }
}

// ---------------------------------------------------------------------------
extern "C" void kernel_launch(void* const* d_in, const int* in_sizes, int n_in,
                              void* d_out, int out_size)
{
    const float* x  = (const float*)d_in[0];
    const float* Wz = (const float*)d_in[1];
    const float* Wi = (const float*)d_in[2];
    const float* Wf = (const float*)d_in[3];
    const float* Wo = (const float*)d_in[4];
    float* out = (float*)d_out;

    dim3 grid(MTOK / BM, (HH * HDm * 4) / (HH * BN) * 0 + (1024 / BN), HH); // (512, 8, 4)
    pregate_gemm<<<grid, 256>>>(x, Wz, Wi, Wf, Wo);
    slstm_scan<<<64, 128>>>(out);
}

// round 4
// speedup vs baseline: 1.8616x; 1.8616x over previous
#include <cuda_runtime.h>
#include <cstdint>

// ---------------------------------------------------------------------------
// Problem constants
// ---------------------------------------------------------------------------
#define HH   4
#define HDm  256
#define Dm   1024
#define Sm   4096
#define Bm   8
#define MTOK (Bm * Sm)   // 32768 tokens

// Gate scratch: (z,i,f,o) interleaved per (token, d).  32768*1024*16B = 512 MB.
__device__ float4 g_gates[(size_t)MTOK * Dm];

// ---------------------------------------------------------------------------
// tf32 helpers (fallback mma.sync path — tcgen05 not available: harness PTX
// targets sm_103 without the 'a' feature suffix)
// ---------------------------------------------------------------------------
__device__ __forceinline__ float f2tf32(float x) {
    unsigned u;
    asm("cvt.rna.tf32.f32 %0, %1;" : "=r"(u) : "f"(x));
    return __uint_as_float(u);
}

__device__ __forceinline__ void mma_tf32(float c[4], const float a[4], const float b[2]) {
    asm volatile(
        "mma.sync.aligned.m16n8k8.row.col.f32.tf32.tf32.f32 "
        "{%0,%1,%2,%3}, {%4,%5,%6,%7}, {%8,%9}, {%0,%1,%2,%3};"
        : "+f"(c[0]), "+f"(c[1]), "+f"(c[2]), "+f"(c[3])
        : "r"(__float_as_uint(a[0])), "r"(__float_as_uint(a[1])),
          "r"(__float_as_uint(a[2])), "r"(__float_as_uint(a[3])),
          "r"(__float_as_uint(b[0])), "r"(__float_as_uint(b[1])));
}

// ---------------------------------------------------------------------------
// Pregate GEMM:  per head h,  out[t, n] = sum_k x[t, h*256+k] * Wg[h][o][k]
// with n = o*4 + g  (gate-interleaved so epilogue writes are contiguous and
// the scan reads one float4 per (token, d)).
//
// BM=128, BN=128, BK=16. 256 threads = 8 warps (2m x 4n), warp tile 64x32
// (4 m-frags x 4 n-frags). Double-buffered SMEM, register-staged LDG, one
// __syncthreads per K-iter. SMEM rows padded to 20 floats (80B) -> the
// fragment LDS pattern is bank-conflict-free.
// ---------------------------------------------------------------------------
#define BM 128
#define BN 128
#define BK 16
#define NITER (HDm / BK)   // 16
#define RST 20             // smem row stride in floats (16 data + 4 pad)

__global__ __launch_bounds__(256, 2) void pregate_gemm(
    const float* __restrict__ x,
    const float* __restrict__ Wz, const float* __restrict__ Wi,
    const float* __restrict__ Wf, const float* __restrict__ Wo)
{
    __shared__ float As[2][BM * RST];
    __shared__ float Bs[2][BN * RST];

    const int tid  = threadIdx.x;
    const int lane = tid & 31;
    const int wid  = tid >> 5;
    const int wm   = wid & 1;        // 2 warps along m (64 rows each)
    const int wn   = wid >> 1;       // 4 warps along n (32 cols each)
    const int grp  = lane >> 2;      // 0..7
    const int tig  = lane & 3;       // 0..3

    const int n0 = blockIdx.x * BN;
    const int m0 = blockIdx.y * BM;
    const int h  = blockIdx.z;

    // Per-thread global load assignment: row = tid>>1 (0..127), 2 float4 each
    // (32B contiguous).  Same row index serves the A row and the B row.
    const int lrow = tid >> 1;
    const int lf   = (tid & 1) * 8;       // float offset within 16-float row

    const float* aptr = x + (size_t)(m0 + lrow) * Dm + h * HDm + lf;
    const int nb_ = n0 + lrow;
    const int g_  = nb_ & 3;
    const int o_  = nb_ >> 2;
    const float* W = (g_ == 0) ? Wz : (g_ == 1) ? Wi : (g_ == 2) ? Wf : Wo;
    const float* bptr = W + ((size_t)(h * HDm + o_)) * HDm + lf;

    const int soff = lrow * RST + lf;     // float index into stage

    float acc[4][4][4];
    #pragma unroll
    for (int mf = 0; mf < 4; mf++)
        #pragma unroll
        for (int nf = 0; nf < 4; nf++)
            #pragma unroll
            for (int i = 0; i < 4; i++) acc[mf][nf][i] = 0.0f;

    // ---- prologue: load + store stage 0 ----
    float4 ra0 = *(const float4*)(aptr);
    float4 ra1 = *(const float4*)(aptr + 4);
    float4 rb0 = *(const float4*)(bptr);
    float4 rb1 = *(const float4*)(bptr + 4);
    {
        float4 a0 = make_float4(f2tf32(ra0.x), f2tf32(ra0.y), f2tf32(ra0.z), f2tf32(ra0.w));
        float4 a1 = make_float4(f2tf32(ra1.x), f2tf32(ra1.y), f2tf32(ra1.z), f2tf32(ra1.w));
        float4 b0 = make_float4(f2tf32(rb0.x), f2tf32(rb0.y), f2tf32(rb0.z), f2tf32(rb0.w));
        float4 b1 = make_float4(f2tf32(rb1.x), f2tf32(rb1.y), f2tf32(rb1.z), f2tf32(rb1.w));
        *(float4*)&As[0][soff]     = a0;
        *(float4*)&As[0][soff + 4] = a1;
        *(float4*)&Bs[0][soff]     = b0;
        *(float4*)&Bs[0][soff + 4] = b1;
    }
    __syncthreads();

    #pragma unroll 1
    for (int it = 0; it < NITER; it++) {
        const int cur = it & 1;
        const int nxt = cur ^ 1;
        const bool more = (it + 1) < NITER;

        // ---- issue next chunk's global loads early ----
        if (more) {
            const int kn = (it + 1) * BK;
            ra0 = *(const float4*)(aptr + kn);
            ra1 = *(const float4*)(aptr + kn + 4);
            rb0 = *(const float4*)(bptr + kn);
            rb1 = *(const float4*)(bptr + kn + 4);
        }

        // ---- compute 2 k8-steps from current stage ----
        #pragma unroll
        for (int kk = 0; kk < BK; kk += 8) {
            float a[4][4];
            #pragma unroll
            for (int mf = 0; mf < 4; mf++) {
                const int mb = wm * 64 + mf * 16;
                a[mf][0] = As[cur][(mb + grp)     * RST + kk + tig];
                a[mf][1] = As[cur][(mb + grp + 8) * RST + kk + tig];
                a[mf][2] = As[cur][(mb + grp)     * RST + kk + tig + 4];
                a[mf][3] = As[cur][(mb + grp + 8) * RST + kk + tig + 4];
            }
            float b[4][2];
            #pragma unroll
            for (int nf = 0; nf < 4; nf++) {
                const int nbr = wn * 32 + nf * 8 + grp;
                b[nf][0] = Bs[cur][nbr * RST + kk + tig];
                b[nf][1] = Bs[cur][nbr * RST + kk + tig + 4];
            }
            #pragma unroll
            for (int mf = 0; mf < 4; mf++)
                #pragma unroll
                for (int nf = 0; nf < 4; nf++)
                    mma_tf32(acc[mf][nf], a[mf], b[nf]);
        }

        // ---- convert + store next stage ----
        if (more) {
            float4 a0 = make_float4(f2tf32(ra0.x), f2tf32(ra0.y), f2tf32(ra0.z), f2tf32(ra0.w));
            float4 a1 = make_float4(f2tf32(ra1.x), f2tf32(ra1.y), f2tf32(ra1.z), f2tf32(ra1.w));
            float4 b0 = make_float4(f2tf32(rb0.x), f2tf32(rb0.y), f2tf32(rb0.z), f2tf32(rb0.w));
            float4 b1 = make_float4(f2tf32(rb1.x), f2tf32(rb1.y), f2tf32(rb1.z), f2tf32(rb1.w));
            *(float4*)&As[nxt][soff]     = a0;
            *(float4*)&As[nxt][soff + 4] = a1;
            *(float4*)&Bs[nxt][soff]     = b0;
            *(float4*)&Bs[nxt][soff + 4] = b1;
        }
        __syncthreads();
    }

    // ---- epilogue: acc -> gate buffer (fp32), contiguous float2 writes ----
    float* gbuf = (float*)g_gates;
    #pragma unroll
    for (int mf = 0; mf < 4; mf++) {
        const int row = m0 + wm * 64 + mf * 16 + grp;
        float* orow = gbuf + (size_t)row * 4096 + h * 1024;
        #pragma unroll
        for (int nf = 0; nf < 4; nf++) {
            const int col = n0 + wn * 32 + nf * 8 + 2 * tig;
            *(float2*)&orow[col]                      = make_float2(acc[mf][nf][0], acc[mf][nf][1]);
            *(float2*)&orow[col + (size_t)8 * 4096]   = make_float2(acc[mf][nf][2], acc[mf][nf][3]);
        }
    }
}

// ---------------------------------------------------------------------------
// Sequential scan: 8192 lanes (b,d), 4096 steps. 128 blocks x 64 threads so
// ~128 SMs participate; PF=16 register prefetch ring (16 LDG.128 in flight
// per thread) to push DRAM toward saturation.
// ---------------------------------------------------------------------------
#define PF 16

__global__ __launch_bounds__(64) void slstm_scan(float* __restrict__ out)
{
    const int gt = blockIdx.x * 64 + threadIdx.x;  // 0..8191
    const int b = gt >> 10;
    const int d = gt & 1023;

    const float4* gp = g_gates + (size_t)b * Sm * Dm + d;
    float* op = out + (size_t)b * Sm * Dm + d;

    float c = 0.0f, n = 0.0f, m = 0.0f;

    float4 buf[PF];
    #pragma unroll
    for (int j = 0; j < PF; j++) buf[j] = gp[(size_t)j * Dm];

    #pragma unroll 1
    for (int s0 = 0; s0 < Sm; s0 += PF) {
        #pragma unroll
        for (int j = 0; j < PF; j++) {
            const float4 gv = buf[j];
            const int sn = s0 + j + PF;
            if (sn < Sm) buf[j] = gp[(size_t)sn * Dm];

            const float zt = gv.x, it = gv.y, ft = gv.z, ot = gv.w;

            // m' = max(f + m, i); single exp for the non-dominant branch
            const float fm = ft + m;
            const bool  fge = (fm >= it);
            const float e  = __expf(-fabsf(fm - it));
            const float i_hat = fge ? e : 1.0f;
            const float f_hat = fge ? 1.0f : e;
            m = fmaxf(fm, it);

            // z = tanh(zt); o = sigmoid(ot)
            const float z = 1.0f - __fdividef(2.0f, __expf(2.0f * zt) + 1.0f);
            const float o = __fdividef(1.0f, 1.0f + __expf(-ot));

            c = f_hat * c + i_hat * z;
            n = f_hat * n + i_hat;

            op[(size_t)(s0 + j) * Dm] = o * __fdividef(c, n + 1e-8f);
        }
    }
}

// ---------------------------------------------------------------------------
extern "C" void kernel_launch(void* const* d_in, const int* in_sizes, int n_in,
                              void* d_out, int out_size)
{
    const float* x  = (const float*)d_in[0];
    const float* Wz = (const float*)d_in[1];
    const float* Wi = (const float*)d_in[2];
    const float* Wf = (const float*)d_in[3];
    const float* Wo = (const float*)d_in[4];
    float* out = (float*)d_out;

    dim3 grid(1024 / BN, MTOK / BM, HH);   // (8, 256, 4); x-fastest shares A tile in L2
    pregate_gemm<<<grid, 256>>>(x, Wz, Wi, Wf, Wo);
    slstm_scan<<<128, 64>>>(out);
}

// round 5
// speedup vs baseline: 2.4833x; 1.3340x over previous
#include <cuda_runtime.h>
#include <cuda_fp16.h>
#include <cstdint>

// ---------------------------------------------------------------------------
// Problem constants
// ---------------------------------------------------------------------------
#define HH   4
#define HDm  256
#define Dm   1024
#define Sm   4096
#define Bm   8
#define MTOK (Bm * Sm)   // 32768 tokens

// Gate scratch: (z,i,f,o) interleaved per (token, d).  32768*1024*16B = 512 MB.
__device__ float4 g_gates[(size_t)MTOK * Dm];

__device__ __forceinline__ uint32_t smem_to_u32(const void* p) {
    uint32_t a;
    asm("{ .reg .u64 t; cvta.to.shared.u64 t, %1; cvt.u32.u64 %0, t; }" : "=r"(a) : "l"(p));
    return a;
}

// ---------------------------------------------------------------------------
// fp16 mma helpers (m16n8k16, f32 accumulate). Same 11-bit effective mantissa
// as tf32, 2x the fallback-HMMA rate and half the LDS/CVT/SMEM cost.
// ---------------------------------------------------------------------------
__device__ __forceinline__ uint32_t packh2(float lo, float hi) {
    __half2 t = __floats2half2_rn(lo, hi);
    return *(uint32_t*)&t;
}

__device__ __forceinline__ void mma_fp16(float c[4], const uint32_t a[4], const uint32_t b[2]) {
    asm volatile(
        "mma.sync.aligned.m16n8k16.row.col.f32.f16.f16.f32 "
        "{%0,%1,%2,%3}, {%4,%5,%6,%7}, {%8,%9}, {%0,%1,%2,%3};"
        : "+f"(c[0]), "+f"(c[1]), "+f"(c[2]), "+f"(c[3])
        : "r"(a[0]), "r"(a[1]), "r"(a[2]), "r"(a[3]), "r"(b[0]), "r"(b[1]));
}

// ---------------------------------------------------------------------------
// Pregate GEMM:  per head h,  out[t, n] = sum_k x[t, h*256+k] * Wg[h][o][k]
// with n = o*4 + g  (gate-interleaved -> scan reads one float4 per (t,d)).
//
// BM=128, BN=128, BK=16, 256 threads = 8 warps (2m x 4n), warp tile 64x32
// (4x4 m16n8k16 fragments). Double-buffered fp16 SMEM (row stride 24 halves:
// conflict-free fragment LDS), register-staged LDG, one barrier per K-iter.
// ---------------------------------------------------------------------------
#define BM 128
#define BN 128
#define BK 16
#define NITER (HDm / BK)   // 16
#define RSTH 24            // smem row stride in halves (16 data + 8 pad)

__global__ __launch_bounds__(256, 2) void pregate_gemm(
    const float* __restrict__ x,
    const float* __restrict__ Wz, const float* __restrict__ Wi,
    const float* __restrict__ Wf, const float* __restrict__ Wo)
{
    __shared__ __half As[2][BM * RSTH];
    __shared__ __half Bs[2][BN * RSTH];

    const int tid  = threadIdx.x;
    const int lane = tid & 31;
    const int wid  = tid >> 5;
    const int wm   = wid & 1;        // 2 warps along m (64 rows each)
    const int wn   = wid >> 1;       // 4 warps along n (32 cols each)
    const int grp  = lane >> 2;      // 0..7
    const int tig  = lane & 3;       // 0..3

    const int n0 = blockIdx.x * BN;
    const int m0 = blockIdx.y * BM;
    const int h  = blockIdx.z;

    // Global load: row = tid>>1 (0..127), 8 contiguous floats at (tid&1)*8.
    const int lrow = tid >> 1;
    const int lf   = (tid & 1) * 8;

    const float* aptr = x + (size_t)(m0 + lrow) * Dm + h * HDm + lf;
    const int nb_ = n0 + lrow;
    const int g_  = nb_ & 3;
    const int o_  = nb_ >> 2;
    const float* W = (g_ == 0) ? Wz : (g_ == 1) ? Wi : (g_ == 2) ? Wf : Wo;
    const float* bptr = W + ((size_t)(h * HDm + o_)) * HDm + lf;

    const int shoff = lrow * RSTH + lf;   // half index into stage

    float acc[4][4][4];
    #pragma unroll
    for (int mf = 0; mf < 4; mf++)
        #pragma unroll
        for (int nf = 0; nf < 4; nf++)
            #pragma unroll
            for (int i = 0; i < 4; i++) acc[mf][nf][i] = 0.0f;

    float4 ra0, ra1, rb0, rb1;

    // ---- prologue: load + convert + store stage 0 ----
    ra0 = *(const float4*)(aptr);
    ra1 = *(const float4*)(aptr + 4);
    rb0 = *(const float4*)(bptr);
    rb1 = *(const float4*)(bptr + 4);
    {
        uint4 pa, pb;
        pa.x = packh2(ra0.x, ra0.y); pa.y = packh2(ra0.z, ra0.w);
        pa.z = packh2(ra1.x, ra1.y); pa.w = packh2(ra1.z, ra1.w);
        pb.x = packh2(rb0.x, rb0.y); pb.y = packh2(rb0.z, rb0.w);
        pb.z = packh2(rb1.x, rb1.y); pb.w = packh2(rb1.z, rb1.w);
        *(uint4*)&As[0][shoff] = pa;
        *(uint4*)&Bs[0][shoff] = pb;
    }
    __syncthreads();

    #pragma unroll 1
    for (int it = 0; it < NITER; it++) {
        const int cur = it & 1;
        const int nxt = cur ^ 1;
        const bool more = (it + 1) < NITER;

        if (more) {
            const int kn = (it + 1) * BK;
            ra0 = *(const float4*)(aptr + kn);
            ra1 = *(const float4*)(aptr + kn + 4);
            rb0 = *(const float4*)(bptr + kn);
            rb1 = *(const float4*)(bptr + kn + 4);
        }

        // ---- one k16 step: 16 HMMA from current stage ----
        {
            const uint32_t* A32 = (const uint32_t*)As[cur];
            const uint32_t* B32 = (const uint32_t*)Bs[cur];
            uint32_t a[4][4];
            #pragma unroll
            for (int mf = 0; mf < 4; mf++) {
                const int mb = wm * 64 + mf * 16;
                a[mf][0] = A32[(mb + grp)     * (RSTH / 2) + tig];
                a[mf][1] = A32[(mb + grp + 8) * (RSTH / 2) + tig];
                a[mf][2] = A32[(mb + grp)     * (RSTH / 2) + tig + 4];
                a[mf][3] = A32[(mb + grp + 8) * (RSTH / 2) + tig + 4];
            }
            uint32_t b[4][2];
            #pragma unroll
            for (int nf = 0; nf < 4; nf++) {
                const int nbr = wn * 32 + nf * 8 + grp;
                b[nf][0] = B32[nbr * (RSTH / 2) + tig];
                b[nf][1] = B32[nbr * (RSTH / 2) + tig + 4];
            }
            #pragma unroll
            for (int mf = 0; mf < 4; mf++)
                #pragma unroll
                for (int nf = 0; nf < 4; nf++)
                    mma_fp16(acc[mf][nf], a[mf], b[nf]);
        }

        if (more) {
            uint4 pa, pb;
            pa.x = packh2(ra0.x, ra0.y); pa.y = packh2(ra0.z, ra0.w);
            pa.z = packh2(ra1.x, ra1.y); pa.w = packh2(ra1.z, ra1.w);
            pb.x = packh2(rb0.x, rb0.y); pb.y = packh2(rb0.z, rb0.w);
            pb.z = packh2(rb1.x, rb1.y); pb.w = packh2(rb1.z, rb1.w);
            *(uint4*)&As[nxt][shoff] = pa;
            *(uint4*)&Bs[nxt][shoff] = pb;
        }
        __syncthreads();
    }

    // ---- epilogue: acc -> gate buffer (fp32), contiguous float2 writes ----
    float* gbuf = (float*)g_gates;
    #pragma unroll
    for (int mf = 0; mf < 4; mf++) {
        const int row = m0 + wm * 64 + mf * 16 + grp;
        float* orow = gbuf + (size_t)row * 4096 + h * 1024;
        #pragma unroll
        for (int nf = 0; nf < 4; nf++) {
            const int col = n0 + wn * 32 + nf * 8 + 2 * tig;
            *(float2*)&orow[col]                      = make_float2(acc[mf][nf][0], acc[mf][nf][1]);
            *(float2*)&orow[col + (size_t)8 * 4096]   = make_float2(acc[mf][nf][2], acc[mf][nf][3]);
        }
    }
}

// ---------------------------------------------------------------------------
// Sequential scan, producer/consumer decoupled.
// 128 blocks x 256 threads: tid 0..63 = compute lanes (one (b,d) each),
// tid 64..255 = loaders streaming gates into a triple-buffered SMEM ring via
// cp.async.cg (deep MLP without touching the compute warps' issue slots).
// ---------------------------------------------------------------------------
#define CH   32                 // steps per chunk
#define NBUF 3
#define NCH  (Sm / CH)          // 128
#define SCAN_SMEM (NBUF * CH * 64 * 16)   // 98304 B

__device__ __forceinline__ void cp_async16(uint32_t smem_addr, const void* gptr) {
    asm volatile("cp.async.cg.shared.global [%0], [%1], 16;"
                 :: "r"(smem_addr), "l"(gptr) : "memory");
}

__global__ __launch_bounds__(256) void slstm_scan(float* __restrict__ out)
{
    extern __shared__ float4 sg[];
    const int tid = threadIdx.x;
    const int b   = blockIdx.x >> 4;           // 8 batches * 16 blocks
    const int d0  = (blockIdx.x & 15) * 64;
    const size_t tb = (size_t)b * Sm;

    const uint32_t sbase = smem_to_u32(sg);
    const float L2E = 1.4426950408889634f;

    if (tid >= 64) {
        const int lt = tid - 64;
        #pragma unroll
        for (int ck = 0; ck < 2; ck++) {
            for (int e = lt; e < CH * 64; e += 192) {
                const int s = ck * CH + (e >> 6);
                cp_async16(sbase + (uint32_t)(ck * (CH * 64) + e) * 16,
                           g_gates + (tb + s) * Dm + d0 + (e & 63));
            }
            asm volatile("cp.async.commit_group;" ::: "memory");
        }
        asm volatile("cp.async.wait_group 1;" ::: "memory");
    }
    __syncthreads();

    float c = 0.0f, n = 0.0f, m = 0.0f;
    float* orow = out + tb * Dm + d0 + (tid & 63);

    #pragma unroll 1
    for (int it = 0; it < NCH; it++) {
        if (tid < 64) {
            const float4* buf = sg + (it % NBUF) * (CH * 64);
            float* op = orow + (size_t)it * CH * Dm;
            #pragma unroll 4
            for (int j = 0; j < CH; j++) {
                const float4 gv = buf[j * 64 + tid];
                const float zt = gv.x, it_ = gv.y, ft = gv.z, ot = gv.w;

                // m' = max(f + m, i); single exp for the non-dominant branch
                const float fm = ft + m;
                const bool  fge = (fm >= it_);
                float e_;
                asm("ex2.approx.f32 %0, %1;" : "=f"(e_) : "f"(-fabsf(fm - it_) * L2E));
                const float i_hat = fge ? e_ : 1.0f;
                const float f_hat = fge ? 1.0f : e_;
                m = fmaxf(fm, it_);

                float z;
                asm("tanh.approx.f32 %0, %1;" : "=f"(z) : "f"(zt));
                float eo;
                asm("ex2.approx.f32 %0, %1;" : "=f"(eo) : "f"(-ot * L2E));
                float o;
                asm("rcp.approx.f32 %0, %1;" : "=f"(o) : "f"(1.0f + eo));

                c = f_hat * c + i_hat * z;
                n = f_hat * n + i_hat;

                float rn_;
                asm("rcp.approx.f32 %0, %1;" : "=f"(rn_) : "f"(n + 1e-8f));
                op[(size_t)j * Dm] = o * (c * rn_);
            }
        } else {
            const int lt = tid - 64;
            const int ck = it + 2;
            if (ck < NCH) {
                for (int e = lt; e < CH * 64; e += 192) {
                    const int s = ck * CH + (e >> 6);
                    cp_async16(sbase + (uint32_t)((ck % NBUF) * (CH * 64) + e) * 16,
                               g_gates + (tb + s) * Dm + d0 + (e & 63));
                }
            }
            asm volatile("cp.async.commit_group;" ::: "memory");
            asm volatile("cp.async.wait_group 1;" ::: "memory");   // chunk it+1 ready
        }
        __syncthreads();
    }
}

// ---------------------------------------------------------------------------
extern "C" void kernel_launch(void* const* d_in, const int* in_sizes, int n_in,
                              void* d_out, int out_size)
{
    const float* x  = (const float*)d_in[0];
    const float* Wz = (const float*)d_in[1];
    const float* Wi = (const float*)d_in[2];
    const float* Wf = (const float*)d_in[3];
    const float* Wo = (const float*)d_in[4];
    float* out = (float*)d_out;

    dim3 grid(1024 / BN, MTOK / BM, HH);   // (8, 256, 4); x-fastest shares A tile in L2
    pregate_gemm<<<grid, 256>>>(x, Wz, Wi, Wf, Wo);

    cudaFuncSetAttribute(slstm_scan, cudaFuncAttributeMaxDynamicSharedMemorySize, SCAN_SMEM);
    slstm_scan<<<128, 256, SCAN_SMEM>>>(out);
}

// round 6
// speedup vs baseline: 2.6744x; 1.0770x over previous
#include <cuda_runtime.h>
#include <cuda_fp16.h>
#include <cstdint>

// ---------------------------------------------------------------------------
// Problem constants
// ---------------------------------------------------------------------------
#define HH   4
#define HDm  256
#define Dm   1024
#define Sm   4096
#define Bm   8
#define MTOK (Bm * Sm)   // 32768 tokens

// Gate scratch: (z,i,f,o) interleaved per (token, d).  512 MB fp32.
__device__ float4 g_gates[(size_t)MTOK * Dm];
// fp16 copies of x and gate-interleaved W for cp.async streaming.
__device__ __half g_xh[(size_t)MTOK * Dm];            // 64 MB
__device__ __half g_wh[(size_t)HH * Dm * HDm];        // 2 MB: [h][n][k], n=o*4+g

__device__ __forceinline__ uint32_t smem_to_u32(const void* p) {
    uint32_t a;
    asm("{ .reg .u64 t; cvta.to.shared.u64 t, %1; cvt.u32.u64 %0, t; }" : "=r"(a) : "l"(p));
    return a;
}
__device__ __forceinline__ void cp_async16(uint32_t smem_addr, const void* gptr) {
    asm volatile("cp.async.cg.shared.global [%0], [%1], 16;"
                 :: "r"(smem_addr), "l"(gptr) : "memory");
}

// ---------------------------------------------------------------------------
// Preconvert: x -> fp16 (same layout), W -> fp16 gate-interleaved [h][n][k].
// ---------------------------------------------------------------------------
__global__ __launch_bounds__(256) void conv_x(const float* __restrict__ x)
{
    const size_t i = ((size_t)blockIdx.x * 256 + threadIdx.x) * 4;
    const float4 v = *(const float4*)(x + i);
    __half2 lo = __floats2half2_rn(v.x, v.y);
    __half2 hi = __floats2half2_rn(v.z, v.w);
    *(uint2*)(g_xh + i) = make_uint2(*(uint32_t*)&lo, *(uint32_t*)&hi);
}

__global__ __launch_bounds__(256) void conv_w(
    const float* __restrict__ Wz, const float* __restrict__ Wi,
    const float* __restrict__ Wf, const float* __restrict__ Wo)
{
    const size_t q = (size_t)blockIdx.x * 256 + threadIdx.x;   // float4 index
    const size_t j = q * 4;
    const int h = (int)(j >> 18);
    const int n = (int)((j >> 8) & 1023);
    const int k = (int)(j & 255);
    const int g = n & 3;
    const int o = n >> 2;
    const float* W = (g == 0) ? Wz : (g == 1) ? Wi : (g == 2) ? Wf : Wo;
    const float4 v = *(const float4*)&W[((size_t)(h * HDm + o)) * HDm + k];
    __half2 lo = __floats2half2_rn(v.x, v.y);
    __half2 hi = __floats2half2_rn(v.z, v.w);
    *(uint2*)(g_wh + j) = make_uint2(*(uint32_t*)&lo, *(uint32_t*)&hi);
}

// ---------------------------------------------------------------------------
// fp16 mma m16n8k16, f32 accumulate
// ---------------------------------------------------------------------------
__device__ __forceinline__ void mma_fp16(float c[4], const uint32_t a[4], const uint32_t b[2]) {
    asm volatile(
        "mma.sync.aligned.m16n8k16.row.col.f32.f16.f16.f32 "
        "{%0,%1,%2,%3}, {%4,%5,%6,%7}, {%8,%9}, {%0,%1,%2,%3};"
        : "+f"(c[0]), "+f"(c[1]), "+f"(c[2]), "+f"(c[3])
        : "r"(a[0]), "r"(a[1]), "r"(a[2]), "r"(a[3]), "r"(b[0]), "r"(b[1]));
}

// ---------------------------------------------------------------------------
// Pregate GEMM: BM=128, BN=128, BK=32 halves, 3-stage cp.async pipeline,
// 256 threads = 8 warps (2m x 4n), warp tile 64x32 (4x4 m16n8k16 frags).
// SMEM rows: 64B data + 16B pad (stride 80B) -> conflict-free fragment LDS.
// One __syncthreads + one cp.async.wait_group per K-iter (8 iters).
// ---------------------------------------------------------------------------
#define BM 128
#define BN 128
#define BKH 32                  // K halves per stage
#define NITER (HDm / BKH)       // 8
#define ROWB 80                 // smem row stride bytes
#define STAGEB (256 * ROWB)     // 20480 B per stage
#define RS32 20                 // row stride in uint32

__global__ __launch_bounds__(256, 2) void pregate_gemm(void)
{
    __shared__ __align__(16) char sm[3 * STAGEB];
    const uint32_t sbase = smem_to_u32(sm);

    const int tid  = threadIdx.x;
    const int lane = tid & 31;
    const int wid  = tid >> 5;
    const int wm   = wid & 1;
    const int wn   = wid >> 1;
    const int grp  = lane >> 2;
    const int tig  = lane & 3;

    const int n0 = blockIdx.x * BN;
    const int m0 = blockIdx.y * BM;
    const int h  = blockIdx.z;

    // cp.async assignment: thread t -> smem row t (A rows 0..127, B rows 128..255)
    const int arr  = tid >> 7;            // 0 = A, 1 = B
    const int row  = tid & 127;
    const __half* gsrc = arr
        ? (g_wh + ((size_t)(h * Dm + n0 + row)) * HDm)
        : (g_xh + (size_t)(m0 + row) * Dm + h * HDm);
    const uint32_t sdst = sbase + (uint32_t)tid * ROWB;

    float acc[4][4][4];
    #pragma unroll
    for (int mf = 0; mf < 4; mf++)
        #pragma unroll
        for (int nf = 0; nf < 4; nf++)
            #pragma unroll
            for (int i = 0; i < 4; i++) acc[mf][nf][i] = 0.0f;

    // ---- prologue: issue stages 0 and 1 ----
    #pragma unroll
    for (int s = 0; s < 2; s++) {
        #pragma unroll
        for (int j = 0; j < 4; j++)
            cp_async16(sdst + s * STAGEB + j * 16, gsrc + s * BKH + j * 8);
        asm volatile("cp.async.commit_group;" ::: "memory");
    }

    #pragma unroll 1
    for (int it = 0; it < NITER; it++) {
        // stage `it` ready
        if (it < NITER - 1) asm volatile("cp.async.wait_group 1;" ::: "memory");
        else                asm volatile("cp.async.wait_group 0;" ::: "memory");
        __syncthreads();

        // issue stage it+2 (its slot, (it+2)%3 == (it-1)%3, was consumed at it-1)
        if (it + 2 < NITER) {
            const uint32_t so = (uint32_t)((it + 2) % 3) * STAGEB;
            const __half* gp = gsrc + (it + 2) * BKH;
            #pragma unroll
            for (int j = 0; j < 4; j++)
                cp_async16(sdst + so + j * 16, gp + j * 8);
            asm volatile("cp.async.commit_group;" ::: "memory");
        }

        // ---- compute stage it: 2 k16 steps, 32 HMMA ----
        const uint32_t* S32 = (const uint32_t*)(sm + (it % 3) * STAGEB);
        #pragma unroll
        for (int kk = 0; kk < 2; kk++) {
            uint32_t a[4][4];
            #pragma unroll
            for (int mf = 0; mf < 4; mf++) {
                const int mb = wm * 64 + mf * 16;
                a[mf][0] = S32[(mb + grp)     * RS32 + kk * 8 + tig];
                a[mf][1] = S32[(mb + grp + 8) * RS32 + kk * 8 + tig];
                a[mf][2] = S32[(mb + grp)     * RS32 + kk * 8 + tig + 4];
                a[mf][3] = S32[(mb + grp + 8) * RS32 + kk * 8 + tig + 4];
            }
            uint32_t b[4][2];
            #pragma unroll
            for (int nf = 0; nf < 4; nf++) {
                const int nbr = 128 + wn * 32 + nf * 8 + grp;
                b[nf][0] = S32[nbr * RS32 + kk * 8 + tig];
                b[nf][1] = S32[nbr * RS32 + kk * 8 + tig + 4];
            }
            #pragma unroll
            for (int mf = 0; mf < 4; mf++)
                #pragma unroll
                for (int nf = 0; nf < 4; nf++)
                    mma_fp16(acc[mf][nf], a[mf], b[nf]);
        }
    }

    // ---- epilogue: acc -> gate buffer (fp32) ----
    float* gbuf = (float*)g_gates;
    #pragma unroll
    for (int mf = 0; mf < 4; mf++) {
        const int r = m0 + wm * 64 + mf * 16 + grp;
        float* orow = gbuf + (size_t)r * 4096 + h * 1024;
        #pragma unroll
        for (int nf = 0; nf < 4; nf++) {
            const int col = n0 + wn * 32 + nf * 8 + 2 * tig;
            *(float2*)&orow[col]                    = make_float2(acc[mf][nf][0], acc[mf][nf][1]);
            *(float2*)&orow[col + (size_t)8 * 4096] = make_float2(acc[mf][nf][2], acc[mf][nf][3]);
        }
    }
}

// ---------------------------------------------------------------------------
// Sequential scan, producer/consumer decoupled.
// 256 blocks (8 b x 32 d-tiles of 32) x 128 threads: tid 0..31 compute,
// tid 32..127 loaders. 4-buffer SMEM ring, loaders 3 chunks ahead.
// ---------------------------------------------------------------------------
#define CH   32
#define NBUF 4
#define NCH  (Sm / CH)                    // 128
#define CHELE (CH * 32)                   // 1024 float4 per chunk
#define SCAN_SMEM (NBUF * CHELE * 16)     // 65536 B

__global__ __launch_bounds__(128) void slstm_scan(float* __restrict__ out)
{
    extern __shared__ float4 sg[];
    const int tid = threadIdx.x;
    const int b   = blockIdx.x >> 5;
    const int d0  = (blockIdx.x & 31) * 32;
    const size_t tb = (size_t)b * Sm;

    const uint32_t sbase = smem_to_u32(sg);
    const float L2E = 1.4426950408889634f;

    // prologue: loaders issue chunks 0,1,2
    if (tid >= 32) {
        const int lt = tid - 32;
        #pragma unroll
        for (int ck = 0; ck < 3; ck++) {
            for (int e = lt; e < CHELE; e += 96) {
                const int s = ck * CH + (e >> 5);
                cp_async16(sbase + (uint32_t)(ck * CHELE + e) * 16,
                           g_gates + (tb + s) * Dm + d0 + (e & 31));
            }
            asm volatile("cp.async.commit_group;" ::: "memory");
        }
        asm volatile("cp.async.wait_group 2;" ::: "memory");   // chunk 0 ready
    }
    __syncthreads();

    float c = 0.0f, n = 0.0f, m = 0.0f;
    float* orow = out + tb * Dm + d0 + (tid & 31);

    #pragma unroll 1
    for (int it = 0; it < NCH; it++) {
        if (tid < 32) {
            const float4* buf = sg + (it % NBUF) * CHELE;
            float* op = orow + (size_t)it * CH * Dm;
            #pragma unroll 4
            for (int j = 0; j < CH; j++) {
                const float4 gv = buf[j * 32 + tid];
                const float zt = gv.x, it_ = gv.y, ft = gv.z, ot = gv.w;

                const float fm = ft + m;
                const bool  fge = (fm >= it_);
                float e_;
                asm("ex2.approx.f32 %0, %1;" : "=f"(e_) : "f"(-fabsf(fm - it_) * L2E));
                const float i_hat = fge ? e_ : 1.0f;
                const float f_hat = fge ? 1.0f : e_;
                m = fmaxf(fm, it_);

                float z;
                asm("tanh.approx.f32 %0, %1;" : "=f"(z) : "f"(zt));
                float eo;
                asm("ex2.approx.f32 %0, %1;" : "=f"(eo) : "f"(-ot * L2E));
                float o;
                asm("rcp.approx.f32 %0, %1;" : "=f"(o) : "f"(1.0f + eo));

                c = f_hat * c + i_hat * z;
                n = f_hat * n + i_hat;

                float rn_;
                asm("rcp.approx.f32 %0, %1;" : "=f"(rn_) : "f"(n + 1e-8f));
                op[(size_t)j * Dm] = o * (c * rn_);
            }
        } else {
            const int lt = tid - 32;
            const int ck = it + 3;
            if (ck < NCH) {
                for (int e = lt; e < CHELE; e += 96) {
                    const int s = ck * CH + (e >> 5);
                    cp_async16(sbase + (uint32_t)((ck % NBUF) * CHELE + e) * 16,
                               g_gates + (tb + s) * Dm + d0 + (e & 31));
                }
            }
            asm volatile("cp.async.commit_group;" ::: "memory");
            asm volatile("cp.async.wait_group 2;" ::: "memory");   // chunk it+1 ready
        }
        __syncthreads();
    }
}

// ---------------------------------------------------------------------------
extern "C" void kernel_launch(void* const* d_in, const int* in_sizes, int n_in,
                              void* d_out, int out_size)
{
    const float* x  = (const float*)d_in[0];
    const float* Wz = (const float*)d_in[1];
    const float* Wi = (const float*)d_in[2];
    const float* Wf = (const float*)d_in[3];
    const float* Wo = (const float*)d_in[4];
    float* out = (float*)d_out;

    conv_x<<<(MTOK * Dm / 4) / 256, 256>>>(x);
    conv_w<<<(HH * Dm * HDm / 4) / 256, 256>>>(Wz, Wi, Wf, Wo);

    dim3 grid(Dm / BN, MTOK / BM, HH);   // (8, 256, 4)
    pregate_gemm<<<grid, 256>>>();

    cudaFuncSetAttribute(slstm_scan, cudaFuncAttributeMaxDynamicSharedMemorySize, SCAN_SMEM);
    slstm_scan<<<256, 128, SCAN_SMEM>>>(out);
}

// round 8
// speedup vs baseline: 2.7901x; 1.0432x over previous
#include <cuda_runtime.h>
#include <cuda_fp16.h>
#include <cstdint>

// ---------------------------------------------------------------------------
// Problem constants
// ---------------------------------------------------------------------------
#define HH   4
#define HDm  256
#define Dm   1024
#define Sm   4096
#define Bm   8
#define MTOK (Bm * Sm)   // 32768 tokens

// Gate scratch: fp32 (z,i,f,o) interleaved per (token, d). 512 MB.
// (fp16 gates tried in R7: rel_err 1.013e-3 > 1e-3 — i/f feed exp(), rounding
//  compounds through the recurrence. fp32 is required here.)
__device__ float4 g_gates[(size_t)MTOK * Dm];
// fp16 copies of x and gate-interleaved W for cp.async streaming.
__device__ __half g_xh[(size_t)MTOK * Dm];            // 64 MB
__device__ __half g_wh[(size_t)HH * Dm * HDm];        // 2 MB: [h][n][k], n=o*4+g

__device__ __forceinline__ uint32_t smem_to_u32(const void* p) {
    uint32_t a;
    asm("{ .reg .u64 t; cvta.to.shared.u64 t, %1; cvt.u32.u64 %0, t; }" : "=r"(a) : "l"(p));
    return a;
}
__device__ __forceinline__ void cp_async16(uint32_t smem_addr, const void* gptr) {
    asm volatile("cp.async.cg.shared.global [%0], [%1], 16;"
                 :: "r"(smem_addr), "l"(gptr) : "memory");
}

// ---------------------------------------------------------------------------
// Preconvert: x -> fp16 (same layout), W -> fp16 gate-interleaved [h][n][k].
// ---------------------------------------------------------------------------
__global__ __launch_bounds__(256) void conv_x(const float* __restrict__ x)
{
    const size_t i = ((size_t)blockIdx.x * 256 + threadIdx.x) * 4;
    const float4 v = *(const float4*)(x + i);
    __half2 lo = __floats2half2_rn(v.x, v.y);
    __half2 hi = __floats2half2_rn(v.z, v.w);
    *(uint2*)(g_xh + i) = make_uint2(*(uint32_t*)&lo, *(uint32_t*)&hi);
}

__global__ __launch_bounds__(256) void conv_w(
    const float* __restrict__ Wz, const float* __restrict__ Wi,
    const float* __restrict__ Wf, const float* __restrict__ Wo)
{
    const size_t q = (size_t)blockIdx.x * 256 + threadIdx.x;   // float4 index
    const size_t j = q * 4;
    const int h = (int)(j >> 18);
    const int n = (int)((j >> 8) & 1023);
    const int k = (int)(j & 255);
    const int g = n & 3;
    const int o = n >> 2;
    const float* W = (g == 0) ? Wz : (g == 1) ? Wi : (g == 2) ? Wf : Wo;
    const float4 v = *(const float4*)&W[((size_t)(h * HDm + o)) * HDm + k];
    __half2 lo = __floats2half2_rn(v.x, v.y);
    __half2 hi = __floats2half2_rn(v.z, v.w);
    *(uint2*)(g_wh + j) = make_uint2(*(uint32_t*)&lo, *(uint32_t*)&hi);
}

// ---------------------------------------------------------------------------
// fp16 mma m16n8k16 + ldmatrix
// ---------------------------------------------------------------------------
__device__ __forceinline__ void mma_fp16(float c[4], const uint32_t a[4], const uint32_t b[2]) {
    asm volatile(
        "mma.sync.aligned.m16n8k16.row.col.f32.f16.f16.f32 "
        "{%0,%1,%2,%3}, {%4,%5,%6,%7}, {%8,%9}, {%0,%1,%2,%3};"
        : "+f"(c[0]), "+f"(c[1]), "+f"(c[2]), "+f"(c[3])
        : "r"(a[0]), "r"(a[1]), "r"(a[2]), "r"(a[3]), "r"(b[0]), "r"(b[1]));
}
__device__ __forceinline__ void ldsm_x4(uint32_t addr, uint32_t r[4]) {
    asm volatile("ldmatrix.sync.aligned.m8n8.x4.shared.b16 {%0,%1,%2,%3}, [%4];"
                 : "=r"(r[0]), "=r"(r[1]), "=r"(r[2]), "=r"(r[3]) : "r"(addr));
}

// ---------------------------------------------------------------------------
// Pregate GEMM: BM=128, BN=128, BK=32 halves, 3-stage cp.async pipeline,
// 256 threads = 8 warps (2m x 4n), warp tile 64x32. Fragments via ldmatrix
// (6 LDSM.x4 per warp per k16). fp32 epilogue (gate-interleaved float2s).
// SMEM rows: 64B data + 16B pad (80B stride).
// ---------------------------------------------------------------------------
#define BM 128
#define BN 128
#define BKH 32                  // K halves per stage
#define NITER (HDm / BKH)       // 8
#define ROWB 80                 // smem row stride bytes
#define STAGEB (256 * ROWB)     // 20480 B per stage

__global__ __launch_bounds__(256, 2) void pregate_gemm(void)
{
    __shared__ __align__(16) char sm[3 * STAGEB];
    const uint32_t sbase = smem_to_u32(sm);

    const int tid  = threadIdx.x;
    const int lane = tid & 31;
    const int wid  = tid >> 5;
    const int wm   = wid & 1;
    const int wn   = wid >> 1;
    const int grp  = lane >> 2;
    const int tig  = lane & 3;

    const int n0 = blockIdx.x * BN;
    const int m0 = blockIdx.y * BM;
    const int h  = blockIdx.z;

    // cp.async: thread t -> smem row t (A rows 0..127, B rows 128..255)
    const int arr  = tid >> 7;
    const int row  = tid & 127;
    const __half* gsrc = arr
        ? (g_wh + ((size_t)(h * Dm + n0 + row)) * HDm)
        : (g_xh + (size_t)(m0 + row) * Dm + h * HDm);
    const uint32_t sdst = sbase + (uint32_t)tid * ROWB;

    // ldmatrix per-lane base offsets (bytes within a stage)
    uint32_t a_off[4], b_off[2];
    #pragma unroll
    for (int mf = 0; mf < 4; mf++)
        a_off[mf] = (uint32_t)((wm * 64 + mf * 16 + (lane & 15)) * ROWB + ((lane >> 4) * 8) * 2);
    #pragma unroll
    for (int p = 0; p < 2; p++)
        b_off[p] = (uint32_t)((128 + wn * 32 + p * 16 + ((lane >> 4) & 1) * 8 + (lane & 7)) * ROWB
                              + (((lane >> 3) & 1) * 8) * 2);

    float acc[4][4][4];
    #pragma unroll
    for (int mf = 0; mf < 4; mf++)
        #pragma unroll
        for (int nf = 0; nf < 4; nf++)
            #pragma unroll
            for (int i = 0; i < 4; i++) acc[mf][nf][i] = 0.0f;

    // ---- prologue: issue stages 0 and 1 ----
    #pragma unroll
    for (int s = 0; s < 2; s++) {
        #pragma unroll
        for (int j = 0; j < 4; j++)
            cp_async16(sdst + s * STAGEB + j * 16, gsrc + s * BKH + j * 8);
        asm volatile("cp.async.commit_group;" ::: "memory");
    }

    #pragma unroll 1
    for (int it = 0; it < NITER; it++) {
        if (it < NITER - 1) asm volatile("cp.async.wait_group 1;" ::: "memory");
        else                asm volatile("cp.async.wait_group 0;" ::: "memory");
        __syncthreads();

        if (it + 2 < NITER) {
            const uint32_t so = (uint32_t)((it + 2) % 3) * STAGEB;
            const __half* gp = gsrc + (it + 2) * BKH;
            #pragma unroll
            for (int j = 0; j < 4; j++)
                cp_async16(sdst + so + j * 16, gp + j * 8);
            asm volatile("cp.async.commit_group;" ::: "memory");
        }

        // ---- compute stage it: 2 k16 steps ----
        const uint32_t stg = sbase + (uint32_t)(it % 3) * STAGEB;
        #pragma unroll
        for (int kk = 0; kk < 2; kk++) {
            const uint32_t ko = (uint32_t)(kk * 32);   // 16 halves = 32 B
            uint32_t a[4][4], b[2][4];
            #pragma unroll
            for (int mf = 0; mf < 4; mf++) ldsm_x4(stg + a_off[mf] + ko, a[mf]);
            #pragma unroll
            for (int p = 0; p < 2; p++)    ldsm_x4(stg + b_off[p] + ko, b[p]);
            #pragma unroll
            for (int mf = 0; mf < 4; mf++)
                #pragma unroll
                for (int nf = 0; nf < 4; nf++)
                    mma_fp16(acc[mf][nf], a[mf], &b[nf >> 1][(nf & 1) * 2]);
        }
    }

    // ---- epilogue: acc -> fp32 gate buffer (contiguous float2 writes) ----
    float* gbuf = (float*)g_gates;
    #pragma unroll
    for (int mf = 0; mf < 4; mf++) {
        const int r = m0 + wm * 64 + mf * 16 + grp;
        float* orow = gbuf + (size_t)r * 4096 + h * 1024;
        #pragma unroll
        for (int nf = 0; nf < 4; nf++) {
            const int col = n0 + wn * 32 + nf * 8 + 2 * tig;
            *(float2*)&orow[col]                    = make_float2(acc[mf][nf][0], acc[mf][nf][1]);
            *(float2*)&orow[col + (size_t)8 * 4096] = make_float2(acc[mf][nf][2], acc[mf][nf][3]);
        }
    }
}

// ---------------------------------------------------------------------------
// Sequential scan: 128 blocks (1 wave) x 256 threads.
// tid 0..63 compute, tid 64..255 loaders. CH=32-step fp32 chunks (32 KB),
// NBUF=4 (128 KB SMEM), loaders run 3 chunks ahead (wait_group 2).
// 4 MUFU per step (sigmoid RCP folded into the c/n RCP).
// ---------------------------------------------------------------------------
#define CH    32
#define NBUF  4
#define NCH   (Sm / CH)                   // 128
#define CHELE (CH * 64)                   // 2048 float4 per chunk
#define SCAN_SMEM (NBUF * CHELE * 16)     // 131072 B

__global__ __launch_bounds__(256) void slstm_scan(float* __restrict__ out)
{
    extern __shared__ float4 sg[];
    const int tid = threadIdx.x;
    const int b   = blockIdx.x >> 4;             // 8 batches x 16 d-tiles of 64
    const int d0  = (blockIdx.x & 15) * 64;
    const size_t tb = (size_t)b * Sm;

    const uint32_t sbase = smem_to_u32(sg);
    const float L2E = 1.4426950408889634f;

    // prologue: loaders issue chunks 0,1,2
    if (tid >= 64) {
        const int lt = tid - 64;
        #pragma unroll
        for (int ck = 0; ck < 3; ck++) {
            for (int e = lt; e < CHELE; e += 192) {
                const int s = ck * CH + (e >> 6);
                cp_async16(sbase + (uint32_t)(ck * CHELE + e) * 16,
                           g_gates + (tb + s) * Dm + d0 + (e & 63));
            }
            asm volatile("cp.async.commit_group;" ::: "memory");
        }
        asm volatile("cp.async.wait_group 2;" ::: "memory");   // chunk 0 ready
    }
    __syncthreads();

    float c = 0.0f, n = 0.0f, m = 0.0f;
    float* orow = out + tb * Dm + d0 + (tid & 63);

    #pragma unroll 1
    for (int it = 0; it < NCH; it++) {
        if (tid < 64) {
            const float4* buf = sg + (it % NBUF) * CHELE;
            float* op = orow + (size_t)it * CH * Dm;
            #pragma unroll 4
            for (int j = 0; j < CH; j++) {
                const float4 gv = buf[j * 64 + tid];
                const float zt = gv.x, it_ = gv.y, ft = gv.z, ot = gv.w;

                const float fm = ft + m;
                const bool  fge = (fm >= it_);
                float e_;
                asm("ex2.approx.f32 %0, %1;" : "=f"(e_) : "f"(-fabsf(fm - it_) * L2E));
                const float i_hat = fge ? e_ : 1.0f;
                const float f_hat = fge ? 1.0f : e_;
                m = fmaxf(fm, it_);

                float z;
                asm("tanh.approx.f32 %0, %1;" : "=f"(z) : "f"(zt));
                float eo;
                asm("ex2.approx.f32 %0, %1;" : "=f"(eo) : "f"(-ot * L2E));

                c = f_hat * c + i_hat * z;
                n = f_hat * n + i_hat;

                // h = sigmoid(ot) * c/(n+eps) = c * rcp((1+eo)*(n+eps))
                const float den = (1.0f + eo) * (n + 1e-8f);
                float r_;
                asm("rcp.approx.f32 %0, %1;" : "=f"(r_) : "f"(den));
                op[(size_t)j * Dm] = c * r_;
            }
        } else {
            const int lt = tid - 64;
            const int ck = it + 3;
            if (ck < NCH) {
                for (int e = lt; e < CHELE; e += 192) {
                    const int s = ck * CH + (e >> 6);
                    cp_async16(sbase + (uint32_t)((ck % NBUF) * CHELE + e) * 16,
                               g_gates + (tb + s) * Dm + d0 + (e & 63));
                }
            }
            asm volatile("cp.async.commit_group;" ::: "memory");
            asm volatile("cp.async.wait_group 2;" ::: "memory");   // chunk it+1 ready
        }
        __syncthreads();
    }
}

// ---------------------------------------------------------------------------
extern "C" void kernel_launch(void* const* d_in, const int* in_sizes, int n_in,
                              void* d_out, int out_size)
{
    const float* x  = (const float*)d_in[0];
    const float* Wz = (const float*)d_in[1];
    const float* Wi = (const float*)d_in[2];
    const float* Wf = (const float*)d_in[3];
    const float* Wo = (const float*)d_in[4];
    float* out = (float*)d_out;

    conv_x<<<(MTOK * Dm / 4) / 256, 256>>>(x);
    conv_w<<<(HH * Dm * HDm / 4) / 256, 256>>>(Wz, Wi, Wf, Wo);

    dim3 grid(Dm / BN, MTOK / BM, HH);   // (8, 256, 4)
    pregate_gemm<<<grid, 256>>>();

    cudaFuncSetAttribute(slstm_scan, cudaFuncAttributeMaxDynamicSharedMemorySize, SCAN_SMEM);
    slstm_scan<<<128, 256, SCAN_SMEM>>>(out);
}

// round 9
// speedup vs baseline: 2.8956x; 1.0378x over previous
#include <cuda_runtime.h>
#include <cuda_fp16.h>
#include <cstdint>

// ---------------------------------------------------------------------------
// Problem constants
// ---------------------------------------------------------------------------
#define HH   4
#define HDm  256
#define Dm   1024
#define Sm   4096
#define Bm   8
#define MTOK (Bm * Sm)   // 32768 tokens

// Gate scratch: fp32 (z,i,f,o) interleaved per (token, d). 512 MB.
// (fp16 gates: rel_err 1.013e-3 > 1e-3 in R7 — i/f feed exp(). fp32 required.)
__device__ float4 g_gates[(size_t)MTOK * Dm];
// fp16 copies of x and gate-interleaved W for cp.async streaming.
__device__ __half g_xh[(size_t)MTOK * Dm];            // 64 MB
__device__ __half g_wh[(size_t)HH * Dm * HDm];        // 2 MB: [h][n][k], n=o*4+g

__device__ __forceinline__ uint32_t smem_to_u32(const void* p) {
    uint32_t a;
    asm("{ .reg .u64 t; cvta.to.shared.u64 t, %1; cvt.u32.u64 %0, t; }" : "=r"(a) : "l"(p));
    return a;
}
__device__ __forceinline__ void cp_async16(uint32_t smem_addr, const void* gptr) {
    asm volatile("cp.async.cg.shared.global [%0], [%1], 16;"
                 :: "r"(smem_addr), "l"(gptr) : "memory");
}

// ---- mbarrier helpers ----
#define MBARRIER_INIT(addr, cnt) \
    asm volatile("mbarrier.init.shared.b64 [%0], %1;" :: "r"((uint32_t)(addr)), "r"((uint32_t)(cnt)) : "memory")
#define MBARRIER_EXPECT_TX(addr, bytes) \
    asm volatile("mbarrier.arrive.expect_tx.shared.b64 _, [%0], %1;" :: "r"((uint32_t)(addr)), "r"((uint32_t)(bytes)) : "memory")
#define MBARRIER_ARRIVE(addr) \
    asm volatile("mbarrier.arrive.shared.b64 _, [%0];" :: "r"((uint32_t)(addr)) : "memory")
#define MBARRIER_WAIT_PARITY(addr, par) do {                                       \
    uint32_t _m = (uint32_t)(addr); uint32_t _p = (uint32_t)(par); uint32_t _d;    \
    asm volatile("{\n\t.reg .pred p;\n\t"                                          \
        "mbarrier.try_wait.parity.acquire.cta.shared::cta.b64 p, [%1], %2;\n\t"    \
        "selp.b32 %0, 1, 0, p;\n\t}" : "=r"(_d) : "r"(_m), "r"(_p) : "memory");    \
    if (!_d) {                                                                     \
        asm volatile("{\n\t.reg .pred P1;\n\t"                                     \
            "WL_%=:\n\t"                                                           \
            "mbarrier.try_wait.parity.acquire.cta.shared::cta.b64 P1, [%0], %1, 0x989680;\n\t" \
            "@P1 bra.uni WD_%=;\n\t"                                               \
            "bra.uni WL_%=;\n\t"                                                   \
            "WD_%=:\n\t}" :: "r"(_m), "r"(_p) : "memory");                         \
    } } while (0)

// 1024-byte bulk async copy (UBLKCP): one instruction per gate row.
__device__ __forceinline__ void cp_bulk(uint32_t smem_addr, const void* gptr,
                                        uint32_t bytes, uint32_t mbar) {
    asm volatile(
        "cp.async.bulk.shared::cluster.global.mbarrier::complete_tx::bytes [%0], [%1], %2, [%3];"
        :: "r"(smem_addr), "l"(gptr), "r"(bytes), "r"(mbar) : "memory");
}

// ---------------------------------------------------------------------------
// Preconvert: x -> fp16 (same layout), W -> fp16 gate-interleaved [h][n][k].
// ---------------------------------------------------------------------------
__global__ __launch_bounds__(256) void conv_x(const float* __restrict__ x)
{
    const size_t i = ((size_t)blockIdx.x * 256 + threadIdx.x) * 4;
    const float4 v = *(const float4*)(x + i);
    __half2 lo = __floats2half2_rn(v.x, v.y);
    __half2 hi = __floats2half2_rn(v.z, v.w);
    *(uint2*)(g_xh + i) = make_uint2(*(uint32_t*)&lo, *(uint32_t*)&hi);
}

__global__ __launch_bounds__(256) void conv_w(
    const float* __restrict__ Wz, const float* __restrict__ Wi,
    const float* __restrict__ Wf, const float* __restrict__ Wo)
{
    const size_t q = (size_t)blockIdx.x * 256 + threadIdx.x;   // float4 index
    const size_t j = q * 4;
    const int h = (int)(j >> 18);
    const int n = (int)((j >> 8) & 1023);
    const int k = (int)(j & 255);
    const int g = n & 3;
    const int o = n >> 2;
    const float* W = (g == 0) ? Wz : (g == 1) ? Wi : (g == 2) ? Wf : Wo;
    const float4 v = *(const float4*)&W[((size_t)(h * HDm + o)) * HDm + k];
    __half2 lo = __floats2half2_rn(v.x, v.y);
    __half2 hi = __floats2half2_rn(v.z, v.w);
    *(uint2*)(g_wh + j) = make_uint2(*(uint32_t*)&lo, *(uint32_t*)&hi);
}

// ---------------------------------------------------------------------------
// fp16 mma m16n8k16 + ldmatrix
// ---------------------------------------------------------------------------
__device__ __forceinline__ void mma_fp16(float c[4], const uint32_t a[4], const uint32_t b[2]) {
    asm volatile(
        "mma.sync.aligned.m16n8k16.row.col.f32.f16.f16.f32 "
        "{%0,%1,%2,%3}, {%4,%5,%6,%7}, {%8,%9}, {%0,%1,%2,%3};"
        : "+f"(c[0]), "+f"(c[1]), "+f"(c[2]), "+f"(c[3])
        : "r"(a[0]), "r"(a[1]), "r"(a[2]), "r"(a[3]), "r"(b[0]), "r"(b[1]));
}
__device__ __forceinline__ void ldsm_x4(uint32_t addr, uint32_t r[4]) {
    asm volatile("ldmatrix.sync.aligned.m8n8.x4.shared.b16 {%0,%1,%2,%3}, [%4];"
                 : "=r"(r[0]), "=r"(r[1]), "=r"(r[2]), "=r"(r[3]) : "r"(addr));
}

// ---------------------------------------------------------------------------
// Pregate GEMM (unchanged from R8: at the fallback-HMMA ceiling ~24 cyc/HMMA).
// BM=128, BN=128, BK=32 halves, 3-stage cp.async, ldmatrix fragments.
// ---------------------------------------------------------------------------
#define BM 128
#define BN 128
#define BKH 32
#define NITER (HDm / BKH)       // 8
#define ROWB 80
#define STAGEB (256 * ROWB)     // 20480 B

__global__ __launch_bounds__(256, 2) void pregate_gemm(void)
{
    __shared__ __align__(16) char sm[3 * STAGEB];
    const uint32_t sbase = smem_to_u32(sm);

    const int tid  = threadIdx.x;
    const int lane = tid & 31;
    const int wid  = tid >> 5;
    const int wm   = wid & 1;
    const int wn   = wid >> 1;
    const int grp  = lane >> 2;
    const int tig  = lane & 3;

    const int n0 = blockIdx.x * BN;
    const int m0 = blockIdx.y * BM;
    const int h  = blockIdx.z;

    const int arr  = tid >> 7;
    const int row  = tid & 127;
    const __half* gsrc = arr
        ? (g_wh + ((size_t)(h * Dm + n0 + row)) * HDm)
        : (g_xh + (size_t)(m0 + row) * Dm + h * HDm);
    const uint32_t sdst = sbase + (uint32_t)tid * ROWB;

    uint32_t a_off[4], b_off[2];
    #pragma unroll
    for (int mf = 0; mf < 4; mf++)
        a_off[mf] = (uint32_t)((wm * 64 + mf * 16 + (lane & 15)) * ROWB + ((lane >> 4) * 8) * 2);
    #pragma unroll
    for (int p = 0; p < 2; p++)
        b_off[p] = (uint32_t)((128 + wn * 32 + p * 16 + ((lane >> 4) & 1) * 8 + (lane & 7)) * ROWB
                              + (((lane >> 3) & 1) * 8) * 2);

    float acc[4][4][4];
    #pragma unroll
    for (int mf = 0; mf < 4; mf++)
        #pragma unroll
        for (int nf = 0; nf < 4; nf++)
            #pragma unroll
            for (int i = 0; i < 4; i++) acc[mf][nf][i] = 0.0f;

    #pragma unroll
    for (int s = 0; s < 2; s++) {
        #pragma unroll
        for (int j = 0; j < 4; j++)
            cp_async16(sdst + s * STAGEB + j * 16, gsrc + s * BKH + j * 8);
        asm volatile("cp.async.commit_group;" ::: "memory");
    }

    #pragma unroll 1
    for (int it = 0; it < NITER; it++) {
        if (it < NITER - 1) asm volatile("cp.async.wait_group 1;" ::: "memory");
        else                asm volatile("cp.async.wait_group 0;" ::: "memory");
        __syncthreads();

        if (it + 2 < NITER) {
            const uint32_t so = (uint32_t)((it + 2) % 3) * STAGEB;
            const __half* gp = gsrc + (it + 2) * BKH;
            #pragma unroll
            for (int j = 0; j < 4; j++)
                cp_async16(sdst + so + j * 16, gp + j * 8);
            asm volatile("cp.async.commit_group;" ::: "memory");
        }

        const uint32_t stg = sbase + (uint32_t)(it % 3) * STAGEB;
        #pragma unroll
        for (int kk = 0; kk < 2; kk++) {
            const uint32_t ko = (uint32_t)(kk * 32);
            uint32_t a[4][4], b[2][4];
            #pragma unroll
            for (int mf = 0; mf < 4; mf++) ldsm_x4(stg + a_off[mf] + ko, a[mf]);
            #pragma unroll
            for (int p = 0; p < 2; p++)    ldsm_x4(stg + b_off[p] + ko, b[p]);
            #pragma unroll
            for (int mf = 0; mf < 4; mf++)
                #pragma unroll
                for (int nf = 0; nf < 4; nf++)
                    mma_fp16(acc[mf][nf], a[mf], &b[nf >> 1][(nf & 1) * 2]);
        }
    }

    float* gbuf = (float*)g_gates;
    #pragma unroll
    for (int mf = 0; mf < 4; mf++) {
        const int r = m0 + wm * 64 + mf * 16 + grp;
        float* orow = gbuf + (size_t)r * 4096 + h * 1024;
        #pragma unroll
        for (int nf = 0; nf < 4; nf++) {
            const int col = n0 + wn * 32 + nf * 8 + 2 * tig;
            *(float2*)&orow[col]                    = make_float2(acc[mf][nf][0], acc[mf][nf][1]);
            *(float2*)&orow[col + (size_t)8 * 4096] = make_float2(acc[mf][nf][2], acc[mf][nf][3]);
        }
    }
}

// ---------------------------------------------------------------------------
// Sequential scan, bulk-copy edition. 128 blocks x 128 threads.
// tid 0..63 compute; tid 64 is the sole loader, issuing one 1024B
// cp.async.bulk per step-row (64 per chunk) — removes the LDGSTS issue floor
// (16B/8cyc/SMSP ~= 20 GB/s/block) that bound R5-R8 scans.
// CH=64 steps (64 KB/chunk), NBUF=3 (192 KB SMEM), mbarrier full/empty ring.
// ---------------------------------------------------------------------------
#define CH    64
#define NBUF  3
#define NCH   (Sm / CH)                   // 64
#define CHBYTES (CH * 64 * 16)            // 65536
#define MB_FULL(i)  (mb_base + (i) * 8)
#define MB_EMPTY(i) (mb_base + 24 + (i) * 8)
#define SCAN_SMEM (1024 + NBUF * CHBYTES) // 197632 B

__global__ __launch_bounds__(128) void slstm_scan(float* __restrict__ out)
{
    extern __shared__ __align__(16) char smem[];
    const uint32_t mb_base = smem_to_u32(smem);
    float4* sdata = (float4*)(smem + 1024);
    const uint32_t sdata_u32 = mb_base + 1024;

    const int tid = threadIdx.x;
    const int b   = blockIdx.x >> 4;             // 8 batches x 16 d-tiles of 64
    const int d0  = (blockIdx.x & 15) * 64;
    const size_t tb = (size_t)b * Sm;
    const float L2E = 1.4426950408889634f;

    if (tid == 0) {
        #pragma unroll
        for (int i = 0; i < NBUF; i++) {
            MBARRIER_INIT(MB_FULL(i), 1);     // tx-based completion
            MBARRIER_INIT(MB_EMPTY(i), 64);   // 64 compute arrivals
        }
    }
    __syncthreads();

    if (tid == 64) {
        // ---- producer ----
        int stage = 0, ph = 1;                   // phase trick: first waits pass
        #pragma unroll 1
        for (int ck = 0; ck < NCH; ck++) {
            MBARRIER_WAIT_PARITY(MB_EMPTY(stage), ph);
            MBARRIER_EXPECT_TX(MB_FULL(stage), CHBYTES);
            const float4* src = g_gates + (tb + (size_t)ck * CH) * Dm + d0;
            const uint32_t dst = sdata_u32 + (uint32_t)stage * CHBYTES;
            #pragma unroll 4
            for (int j = 0; j < CH; j++)
                cp_bulk(dst + (uint32_t)j * 1024, src + (size_t)j * Dm, 1024, MB_FULL(stage));
            if (++stage == NBUF) { stage = 0; ph ^= 1; }
        }
    } else if (tid < 64) {
        // ---- consumer ----
        float c = 0.0f, n = 0.0f, m = 0.0f;
        float* orow = out + tb * Dm + d0 + tid;
        int stage = 0, ph = 0;
        #pragma unroll 1
        for (int ck = 0; ck < NCH; ck++) {
            MBARRIER_WAIT_PARITY(MB_FULL(stage), ph);
            const float4* buf = sdata + stage * (CHBYTES / 16);
            float* op = orow + (size_t)ck * CH * Dm;
            #pragma unroll 4
            for (int j = 0; j < CH; j++) {
                const float4 gv = buf[j * 64 + tid];
                const float zt = gv.x, it_ = gv.y, ft = gv.z, ot = gv.w;

                const float fm = ft + m;
                const bool  fge = (fm >= it_);
                float e_;
                asm("ex2.approx.f32 %0, %1;" : "=f"(e_) : "f"(-fabsf(fm - it_) * L2E));
                const float i_hat = fge ? e_ : 1.0f;
                const float f_hat = fge ? 1.0f : e_;
                m = fmaxf(fm, it_);

                float z;
                asm("tanh.approx.f32 %0, %1;" : "=f"(z) : "f"(zt));
                float eo;
                asm("ex2.approx.f32 %0, %1;" : "=f"(eo) : "f"(-ot * L2E));

                c = f_hat * c + i_hat * z;
                n = f_hat * n + i_hat;

                // h = sigmoid(ot) * c/(n+eps) = c * rcp((1+eo)*(n+eps))
                const float den = (1.0f + eo) * (n + 1e-8f);
                float r_;
                asm("rcp.approx.f32 %0, %1;" : "=f"(r_) : "f"(den));
                op[(size_t)j * Dm] = c * r_;
            }
            MBARRIER_ARRIVE(MB_EMPTY(stage));
            if (++stage == NBUF) { stage = 0; ph ^= 1; }
        }
    }
    // tid 65..127: exit after init.
}

// ---------------------------------------------------------------------------
extern "C" void kernel_launch(void* const* d_in, const int* in_sizes, int n_in,
                              void* d_out, int out_size)
{
    const float* x  = (const float*)d_in[0];
    const float* Wz = (const float*)d_in[1];
    const float* Wi = (const float*)d_in[2];
    const float* Wf = (const float*)d_in[3];
    const float* Wo = (const float*)d_in[4];
    float* out = (float*)d_out;

    conv_x<<<(MTOK * Dm / 4) / 256, 256>>>(x);
    conv_w<<<(HH * Dm * HDm / 4) / 256, 256>>>(Wz, Wi, Wf, Wo);

    dim3 grid(Dm / BN, MTOK / BM, HH);   // (8, 256, 4)
    pregate_gemm<<<grid, 256>>>();

    cudaFuncSetAttribute(slstm_scan, cudaFuncAttributeMaxDynamicSharedMemorySize, SCAN_SMEM);
    slstm_scan<<<128, 128, SCAN_SMEM>>>(out);
}